// round 1
// baseline (speedup 1.0000x reference)
#include <cuda_runtime.h>
#include <math.h>

#define EN   262144
#define NN   65536
#define RTT  8000
#define HH   64
#define BQn  40
#define RRn  200
#define NLy  3
#define SLOPE 0.22916666666666666f

// ---------------- device scratch (no allocs allowed) ----------------
__device__ float g_node[NN*HH];
__device__ float g_nacc[NN*HH];
__device__ float g_projA[NN*HH];
__device__ float g_projB[NN*HH];
__device__ float g_rel[RTT*HH];
__device__ float g_racc[RTT*HH];
__device__ float g_pr[RTT*HH];
__device__ float g_pq[RTT*HH];
__device__ float g_finals[NLy*RTT*HH];
__device__ float g_fin[RTT*HH];
__device__ float g_Ar[RTT];
__device__ float g_Aq[RTT];
__device__ float g_Br[RTT];
__device__ float g_Bq[RTT];
__device__ float g_asum[NN];
__device__ float g_bsum[RTT];
__device__ float g_ae[EN];
__device__ float g_be[EN];
__device__ float g_en2[EN];
__device__ float g_dinv[NN];
__device__ float g_loop[BQn*HH];
__device__ int   g_qrows[BQn];

__device__ __forceinline__ float actf(float x){ return x >= 0.f ? x : x*SLOPE; }

__device__ __forceinline__ void red4(float* p, float4 v){
    asm volatile("red.global.add.v4.f32 [%0], {%1,%2,%3,%4};"
        :: "l"(__cvta_generic_to_global(p)),
           "f"(v.x), "f"(v.y), "f"(v.z), "f"(v.w) : "memory");
}

// ---------------- init kernels ----------------
__global__ void k_zero_init(){
    int i = blockIdx.x*blockDim.x + threadIdx.x;
    if (i < RTT*HH) g_rel[i] = 0.f;
    if (i < NN)     g_asum[i] = 0.f;   // used as deg accumulator first
}

__global__ void k_zero_layer(){
    int i = blockIdx.x*blockDim.x + threadIdx.x;
    float4 z = make_float4(0.f,0.f,0.f,0.f);
    if (i < NN*HH/4)  ((float4*)g_nacc)[i] = z;
    if (i < RTT*HH/4) ((float4*)g_racc)[i] = z;
    if (i < NN/4)     ((float4*)g_asum)[i] = z;
    if (i < RTT/4)    ((float4*)g_bsum)[i] = z;
}

__global__ void k_node_init(const int* __restrict__ labels, const float* __restrict__ pos_emb){
    int idx = blockIdx.x*blockDim.x + threadIdx.x;
    if (idx >= NN*HH) return;
    int n = idx >> 6, h = idx & 63;
    int p = labels[2*n]*4 + labels[2*n+1];
    g_node[idx] = pos_emb[p*HH + h];
}

__global__ void k_set_rows(const int* __restrict__ posns, const float* __restrict__ src){
    int idx = blockIdx.x*blockDim.x + threadIdx.x;
    if (idx >= BQn*HH) return;
    int q = idx >> 6, h = idx & 63;
    g_node[posns[q]*HH + h] = src[h];
}

__global__ void k_rel_init(const int* __restrict__ qrel, const float* __restrict__ srel,
                           const float* __restrict__ lemb){
    int idx = blockIdx.x*blockDim.x + threadIdx.x;
    if (idx >= BQn*HH) return;
    int q = idx >> 6, h = idx & 63;
    int qrow = qrel[q] + q*RRn;
    if (h == 0) g_qrows[q] = qrow;
    g_rel[qrow*HH + h] = srel[h];
    g_loop[idx] = lemb[h];
}

__global__ void k_deg(const int* __restrict__ row){
    int e = blockIdx.x*blockDim.x + threadIdx.x;
    if (e >= EN) return;
    atomicAdd(&g_asum[row[e]], 1.0f);
}

__global__ void k_dinv(){
    int n = blockIdx.x*blockDim.x + threadIdx.x;
    if (n >= NN) return;
    float d = g_asum[n];
    g_dinv[n] = d > 0.f ? 1.0f/sqrtf(d) : 0.f;
}

__global__ void k_en2(const int* __restrict__ col, const int* __restrict__ row){
    int e = blockIdx.x*blockDim.x + threadIdx.x;
    if (e >= EN) return;
    float t = g_dinv[row[e]]*g_dinv[col[e]];
    g_en2[e] = t*t;
}

// ---------------- 64x64 projection GEMM: out[M,64] = in[M,64] @ W[.,co:co+64]^T ----------------
__global__ __launch_bounds__(256) void k_proj64(const float* __restrict__ in,
                                                const float* __restrict__ W,
                                                int wstride, int coloff,
                                                float* __restrict__ out, int acc){
    __shared__ float Wt[64][66];   // Wt[k][o]
    __shared__ float In[64][64];
    int t = threadIdx.x;
    int rowbase = blockIdx.x * 64;
    for (int idx = t; idx < 4096; idx += 256){
        int o = idx >> 6, k = idx & 63;
        Wt[k][o] = W[o*wstride + coloff + k];
    }
    {
        const float4* in4 = (const float4*)(in + rowbase*HH);
        float4* In4 = (float4*)&In[0][0];
        for (int idx = t; idx < 1024; idx += 256) In4[idx] = in4[idx];
    }
    __syncthreads();
    int ox = t & 31, ry = t >> 5;  // warp ry: rows ry*8..+7 ; lane: outputs 2ox,2ox+1
    float2 a8[8];
    #pragma unroll
    for (int r=0;r<8;r++) a8[r] = make_float2(0.f,0.f);
    #pragma unroll 4
    for (int k=0;k<64;k+=4){
        float2 w0 = *(const float2*)&Wt[k+0][2*ox];
        float2 w1 = *(const float2*)&Wt[k+1][2*ox];
        float2 w2 = *(const float2*)&Wt[k+2][2*ox];
        float2 w3 = *(const float2*)&Wt[k+3][2*ox];
        #pragma unroll
        for (int r=0;r<8;r++){
            float4 v = *(const float4*)&In[ry*8+r][k];
            a8[r].x = fmaf(v.x,w0.x,a8[r].x); a8[r].y = fmaf(v.x,w0.y,a8[r].y);
            a8[r].x = fmaf(v.y,w1.x,a8[r].x); a8[r].y = fmaf(v.y,w1.y,a8[r].y);
            a8[r].x = fmaf(v.z,w2.x,a8[r].x); a8[r].y = fmaf(v.z,w2.y,a8[r].y);
            a8[r].x = fmaf(v.w,w3.x,a8[r].x); a8[r].y = fmaf(v.w,w3.y,a8[r].y);
        }
    }
    #pragma unroll
    for (int r=0;r<8;r++){
        float2* op = (float2*)(out + (rowbase + ry*8 + r)*HH + 2*ox);
        float2 v = a8[r];
        if (acc){ float2 o = *op; v.x += o.x; v.y += o.y; }
        *op = v;
    }
}

// ---------------- act(+bias)(+resid) + LayerNorm, warp per row ----------------
__global__ void k_actln(const float* __restrict__ x, const float* __restrict__ bias,
                        const float* __restrict__ resid, float* __restrict__ out,
                        float* __restrict__ out2, int M){
    int w = (blockIdx.x*blockDim.x + threadIdx.x) >> 5;
    int lane = threadIdx.x & 31;
    if (w >= M) return;
    float2 v = *(const float2*)(x + w*HH + 2*lane);
    float2 b = *(const float2*)(bias + 2*lane);
    float y0 = actf(v.x + b.x), y1 = actf(v.y + b.y);
    if (resid){
        float2 rv = *(const float2*)(resid + w*HH + 2*lane);
        y0 += rv.x; y1 += rv.y;
    }
    float s = y0 + y1, sq = y0*y0 + y1*y1;
    #pragma unroll
    for (int o=16;o;o>>=1){ s += __shfl_xor_sync(0xffffffffu,s,o); sq += __shfl_xor_sync(0xffffffffu,sq,o); }
    float m = s*(1.f/64.f);
    float var = sq*(1.f/64.f) - m*m;
    float inv = rsqrtf(var + 1e-5f);
    float2 ov = make_float2((y0-m)*inv, (y1-m)*inv);
    *(float2*)(out + w*HH + 2*lane) = ov;
    if (out2) *(float2*)(out2 + w*HH + 2*lane) = ov;
}

// ---------------- per-relation attention scalars ----------------
__global__ void k_relscal(const float* __restrict__ Wa, const float* __restrict__ Wb){
    int w = (blockIdx.x*blockDim.x + threadIdx.x) >> 5;
    int lane = threadIdx.x & 31;
    if (w >= RTT) return;
    float2 v = *(const float2*)(g_rel + w*HH + 2*lane);
    float a0 = actf(v.x), a1 = actf(v.y);
    float2 wa1 = *(const float2*)(Wa + 2*lane);
    float2 wa2 = *(const float2*)(Wa + 64 + 2*lane);
    float2 wb1 = *(const float2*)(Wb + 2*lane);
    float2 wb2 = *(const float2*)(Wb + 64 + 2*lane);
    float sar = a0*wa1.x + a1*wa1.y;
    float saq = a0*wa2.x + a1*wa2.y;
    float sbr = v.x*wb1.x + v.y*wb1.y;
    float sbq = v.x*wb2.x + v.y*wb2.y;
    #pragma unroll
    for (int o=16;o;o>>=1){
        sar += __shfl_xor_sync(0xffffffffu,sar,o);
        saq += __shfl_xor_sync(0xffffffffu,saq,o);
        sbr += __shfl_xor_sync(0xffffffffu,sbr,o);
        sbq += __shfl_xor_sync(0xffffffffu,sbq,o);
    }
    if (lane == 0){ g_Ar[w]=sar; g_Aq[w]=saq; g_Br[w]=sbr; g_Bq[w]=sbq; }
}

// ---------------- edge attention coefficients ----------------
__global__ void k_edge_att(const int* __restrict__ et, const int* __restrict__ eq,
                           const int* __restrict__ row,
                           const float* __restrict__ ba, const float* __restrict__ bb){
    int e = blockIdx.x*blockDim.x + threadIdx.x;
    if (e >= EN) return;
    int t = et[e], q = eq[e];
    float a = expf(g_Ar[t] + g_Aq[q] + ba[0]);
    float b = expf(g_Br[t] + g_Bq[q] + bb[0]);
    g_ae[e] = a; g_be[e] = b;
    atomicAdd(&g_asum[row[e]], a);
    atomicAdd(&g_bsum[t], b);
}

// ---------------- edge message -> node aggregation ----------------
__global__ void k_edge_msg(const int* __restrict__ col, const int* __restrict__ row,
                           const int* __restrict__ et, const int* __restrict__ eq,
                           const float* __restrict__ bmsg){
    int idx = blockIdx.x*blockDim.x + threadIdx.x;
    int e = idx >> 4, j = idx & 15;
    if (e >= EN) return;
    int c = col[e], r = row[e], t = et[e], q = eq[e];
    // faithful double index: (a_sum[row] + 1e-10)[row]
    float coef = g_ae[e] / (g_asum[row[r]] + 1e-10f) * g_en2[e];
    float4 ph = *(const float4*)&g_projA[c*HH + 4*j];
    float4 pr = *(const float4*)&g_pr[t*HH + 4*j];
    float4 pq = *(const float4*)&g_pq[q*HH + 4*j];
    float4 bm = *(const float4*)&bmsg[4*j];
    float4 v;
    v.x = actf(ph.x+pr.x+pq.x+bm.x)*coef;
    v.y = actf(ph.y+pr.y+pq.y+bm.y)*coef;
    v.z = actf(ph.z+pr.z+pq.z+bm.z)*coef;
    v.w = actf(ph.w+pr.w+pq.w+bm.w)*coef;
    red4(&g_nacc[r*HH + 4*j], v);
}

// ---------------- edge ht2r -> relation aggregation ----------------
__global__ void k_edge_ht2r(const int* __restrict__ col, const int* __restrict__ row,
                            const int* __restrict__ et, const int* __restrict__ eq,
                            const float* __restrict__ bht){
    int idx = blockIdx.x*blockDim.x + threadIdx.x;
    int e = idx >> 4, j = idx & 15;
    if (e >= EN) return;
    int c = col[e], r = row[e], t = et[e], q = eq[e];
    // faithful double index: (b_sum[edge_type] + 1e-10)[edge_type]
    float coef = g_be[e] / (g_bsum[et[t]] + 1e-10f);
    float4 ph = *(const float4*)&g_projA[c*HH + 4*j];
    float4 pt = *(const float4*)&g_projB[r*HH + 4*j];
    float4 pq = *(const float4*)&g_pq[q*HH + 4*j];
    float4 bm = *(const float4*)&bht[4*j];
    float4 v;
    v.x = actf(ph.x+pt.x+pq.x+bm.x)*coef;
    v.y = actf(ph.y+pt.y+pq.y+bm.y)*coef;
    v.z = actf(ph.z+pt.z+pq.z+bm.z)*coef;
    v.w = actf(ph.w+pt.w+pq.w+bm.w)*coef;
    red4(&g_racc[t*HH + 4*j], v);
}

// ---------------- loop update (40 rows) ----------------
__global__ void k_loop(const float* __restrict__ Wl, const float* __restrict__ bl){
    __shared__ float cat[128];
    __shared__ float ps[2], pq2[2];
    int q = blockIdx.x, t = threadIdx.x;   // 64 threads
    int qrow = g_qrows[q];
    float lv = g_loop[q*HH + t];
    cat[t] = lv;
    cat[64+t] = g_rel[qrow*HH + t];
    __syncthreads();
    float s = bl[t];
    #pragma unroll 8
    for (int k=0;k<128;k++) s = fmaf(cat[k], Wl[t*128+k], s);
    float y = lv + actf(s);
    float ss = y, sq = y*y;
    #pragma unroll
    for (int o=16;o;o>>=1){ ss += __shfl_xor_sync(0xffffffffu,ss,o); sq += __shfl_xor_sync(0xffffffffu,sq,o); }
    if ((t&31)==0){ ps[t>>5]=ss; pq2[t>>5]=sq; }
    __syncthreads();
    float S = ps[0]+ps[1], Q = pq2[0]+pq2[1];
    float m = S*(1.f/64.f);
    float var = Q*(1.f/64.f) - m*m;
    float inv = rsqrtf(var + 1e-5f);
    g_loop[q*HH + t] = (y-m)*inv;
}

// ---------------- output means ----------------
__global__ void k_mean(float* __restrict__ out){
    int idx = blockIdx.x*blockDim.x + threadIdx.x;
    if (idx >= 8*201*64) return;
    int h = idx & 63;
    int rb = idx >> 6;
    int r = rb % 201;
    int b = rb / 201;
    float s = 0.f;
    if (r < 200){
        #pragma unroll
        for (int s5=0;s5<5;s5++) s += g_fin[(b*1000 + s5*200 + r)*HH + h];
    } else {
        #pragma unroll
        for (int s5=0;s5<5;s5++) s += g_loop[(b*5 + s5)*HH + h];
    }
    out[idx] = s * 0.2f;
}

// ---------------- host ----------------
struct Ptrs {
    const int *ei,*et,*eq,*hp,*tp,*qr,*lab;
    const float *pos,*srel,*lemb,*Wmsg,*bmsg,*Wht,*bht,*Wa,*ba,*Wb,*bb,*Wl,*bl,*We,*be,*Wr,*br,*Wf,*bf;
};

static void resolve(void* const* d, const int* sz, int n, Ptrs& p){
    int gi, wi;
    if (sz[0] == 2*EN){
        gi = 0;
        wi = (n > 10 && sz[7] == 1 && sz[8] == 1 && sz[9] == 1) ? 10 : 7;
    } else {
        wi = 0; gi = 19;
    }
    p.ei  = (const int*)d[gi+0]; p.et = (const int*)d[gi+1]; p.eq = (const int*)d[gi+2];
    p.hp  = (const int*)d[gi+3]; p.tp = (const int*)d[gi+4]; p.qr = (const int*)d[gi+5];
    p.lab = (const int*)d[gi+6];
    p.pos  = (const float*)d[wi+0];  p.srel = (const float*)d[wi+1];  p.lemb = (const float*)d[wi+2];
    p.Wmsg = (const float*)d[wi+3];  p.bmsg = (const float*)d[wi+4];
    p.Wht  = (const float*)d[wi+5];  p.bht  = (const float*)d[wi+6];
    p.Wa   = (const float*)d[wi+7];  p.ba   = (const float*)d[wi+8];
    p.Wb   = (const float*)d[wi+9];  p.bb   = (const float*)d[wi+10];
    p.Wl   = (const float*)d[wi+11]; p.bl   = (const float*)d[wi+12];
    p.We   = (const float*)d[wi+13]; p.be   = (const float*)d[wi+14];
    p.Wr   = (const float*)d[wi+15]; p.br   = (const float*)d[wi+16];
    p.Wf   = (const float*)d[wi+17]; p.bf   = (const float*)d[wi+18];
}

extern "C" void kernel_launch(void* const* d_in, const int* in_sizes, int n_in,
                              void* d_out, int out_size){
    Ptrs p; resolve(d_in, in_sizes, n_in, p);
    const int* col = p.ei;
    const int* row = p.ei + EN;

    float *s_node, *s_nacc, *s_projA, *s_projB, *s_rel, *s_racc, *s_pr, *s_pq, *s_finals, *s_fin;
    cudaGetSymbolAddress((void**)&s_node,  g_node);
    cudaGetSymbolAddress((void**)&s_nacc,  g_nacc);
    cudaGetSymbolAddress((void**)&s_projA, g_projA);
    cudaGetSymbolAddress((void**)&s_projB, g_projB);
    cudaGetSymbolAddress((void**)&s_rel,   g_rel);
    cudaGetSymbolAddress((void**)&s_racc,  g_racc);
    cudaGetSymbolAddress((void**)&s_pr,    g_pr);
    cudaGetSymbolAddress((void**)&s_pq,    g_pq);
    cudaGetSymbolAddress((void**)&s_finals,g_finals);
    cudaGetSymbolAddress((void**)&s_fin,   g_fin);

    // ---- init ----
    k_zero_init<<<2000,256>>>();
    k_node_init<<<NN*HH/256,256>>>(p.lab, p.pos);
    k_set_rows<<<(BQn*HH+255)/256,256>>>(p.hp, p.pos + 0*HH);
    k_set_rows<<<(BQn*HH+255)/256,256>>>(p.tp, p.pos + 1*HH);
    k_rel_init<<<(BQn*HH+255)/256,256>>>(p.qr, p.srel, p.lemb);
    k_deg<<<EN/256,256>>>(row);
    k_dinv<<<NN/256,256>>>();
    k_en2<<<EN/256,256>>>(col, row);

    for (int i = 0; i < NLy; i++){
        const float* Wmsg = p.Wmsg + i*HH*192;
        const float* bmsg = p.bmsg + i*HH;
        const float* Wht  = p.Wht  + i*HH*192;
        const float* bht  = p.bht  + i*HH;
        const float* Wa   = p.Wa + i*128;
        const float* Wb   = p.Wb + i*128;
        const float* We   = p.We + i*HH*HH;
        const float* be   = p.be + i*HH;
        const float* Wr   = p.Wr + i*HH*HH;
        const float* br   = p.br + i*HH;
        const float* Wl   = p.Wl + i*HH*128;
        const float* bl   = p.bl + i*HH;

        k_zero_layer<<<4096,256>>>();
        k_relscal<<<RTT*32/256,256>>>(Wa, Wb);

        // projections for msg phase
        k_proj64<<<RTT/64,256>>>(s_rel,  Wmsg, 192, 64,  s_pr,   0);  // Pr
        k_proj64<<<RTT/64,256>>>(s_rel,  Wmsg, 192, 128, s_pq,   0);  // Pq
        k_proj64<<<NN/64, 256>>>(s_node, Wmsg, 192, 0,   s_projA,0);  // Ph

        k_edge_att<<<EN/256,256>>>(p.et, p.eq, row, p.ba + i, p.bb + i);
        k_edge_msg<<<EN*16/256,256>>>(col, row, p.et, p.eq, bmsg);

        // entity transform: node = LN(act(nacc @ We^T + be))
        k_proj64<<<NN/64,256>>>(s_nacc, We, 64, 0, s_projA, 0);
        k_actln<<<NN*32/256,256>>>(s_projA, be, (const float*)0, s_node, (float*)0, NN);

        // projections for ht2r phase
        k_proj64<<<NN/64, 256>>>(s_node, Wht, 192, 0,   s_projA, 0);  // Ph2
        k_proj64<<<NN/64, 256>>>(s_node, Wht, 192, 64,  s_projB, 0);  // Pt2
        k_proj64<<<RTT/64,256>>>(s_rel,  Wht, 192, 128, s_pq,    0);  // Pq2

        k_edge_ht2r<<<EN*16/256,256>>>(col, row, p.et, p.eq, bht);

        // relation update: rel = LN(act(racc @ Wr^T + br) + rel); finals[i] = rel
        k_proj64<<<RTT/64,256>>>(s_racc, Wr, 64, 0, s_pr, 0);
        k_actln<<<RTT*32/256,256>>>(s_pr, br, s_rel, s_rel, s_finals + i*RTT*HH, RTT);

        k_loop<<<BQn,64>>>(Wl, bl);
    }

    // final: fin = LN(act(concat(finals) @ Wf^T + bf))
    k_proj64<<<RTT/64,256>>>(s_finals + 0*RTT*HH, p.Wf, 192, 0,   s_fin, 0);
    k_proj64<<<RTT/64,256>>>(s_finals + 1*RTT*HH, p.Wf, 192, 64,  s_fin, 1);
    k_proj64<<<RTT/64,256>>>(s_finals + 2*RTT*HH, p.Wf, 192, 128, s_fin, 1);
    k_actln<<<RTT*32/256,256>>>(s_fin, p.bf, (const float*)0, s_fin, (float*)0, RTT);

    k_mean<<<(8*201*64+255)/256,256>>>((float*)d_out);
}

// round 2
// speedup vs baseline: 1.2004x; 1.2004x over previous
#include <cuda_runtime.h>
#include <math.h>

#define EN   262144
#define NN   65536
#define RTT  8000
#define HH   64
#define BQn  40
#define RRn  200
#define SLOPE 0.22916666666666666f

typedef unsigned long long ull;

// ---------------- device scratch (no allocs allowed) ----------------
__device__ float g_node[NN*HH], g_nacc[NN*HH], g_projA[NN*HH], g_projB[NN*HH];
__device__ float g_rel[RTT*HH], g_racc[RTT*HH], g_pr[RTT*HH], g_pq[RTT*HH];
__device__ float g_finals[3*RTT*HH], g_fin[RTT*HH];
__device__ float g_Ar[RTT], g_Aq[RTT], g_Br[RTT], g_Bq[RTT];
__device__ float g_asum[NN], g_bsum[RTT], g_dinv2[NN];
__device__ float g_aes[EN], g_bes[EN];
__device__ float g_loop[BQn*HH];
__device__ int   g_qrows[BQn];
__device__ int   g_cnt_n[NN], g_off_n[NN+1], g_cur_n[NN];
__device__ int   g_cnt_t[RTT], g_off_t[RTT+1], g_cur_t[RTT];
__device__ int   g_aux[64];
__device__ int4  g_recN[EN];   // (col, et, eq, 0) sorted by row
__device__ int4  g_recT[EN];   // (col, row, eq, 0) sorted by edge_type

__device__ __forceinline__ float actf(float x){ return x >= 0.f ? x : x*SLOPE; }

__device__ __forceinline__ ull pk2(float x, float y){
    ull r; asm("mov.b64 %0, {%1, %2};" : "=l"(r) : "f"(x), "f"(y)); return r;
}
__device__ __forceinline__ void upk2(ull v, float& x, float& y){
    asm("mov.b64 {%0, %1}, %2;" : "=f"(x), "=f"(y) : "l"(v));
}
__device__ __forceinline__ void ffma2(ull& d, ull a, ull b){
    asm("fma.rn.f32x2 %0, %1, %2, %0;" : "+l"(d) : "l"(a), "l"(b));
}

// ---------------- init kernels ----------------
__global__ void k_zero(){
    int i = blockIdx.x*blockDim.x + threadIdx.x;
    if (i < RTT*HH) g_rel[i] = 0.f;
    if (i < NN)     g_cnt_n[i] = 0;
    if (i < RTT)    g_cnt_t[i] = 0;
}

__global__ void k_node_init(const int* __restrict__ labels, const float* __restrict__ pos_emb){
    int idx = blockIdx.x*blockDim.x + threadIdx.x;
    if (idx >= NN*HH) return;
    int n = idx >> 6, h = idx & 63;
    int p = labels[2*n]*4 + labels[2*n+1];
    g_node[idx] = pos_emb[p*HH + h];
}

__global__ void k_set_rows(const int* __restrict__ posns, const float* __restrict__ src){
    int idx = blockIdx.x*blockDim.x + threadIdx.x;
    if (idx >= BQn*HH) return;
    int q = idx >> 6, h = idx & 63;
    g_node[posns[q]*HH + h] = src[h];
}

__global__ void k_rel_init(const int* __restrict__ qrel, const float* __restrict__ srel,
                           const float* __restrict__ lemb){
    int idx = blockIdx.x*blockDim.x + threadIdx.x;
    if (idx >= BQn*HH) return;
    int q = idx >> 6, h = idx & 63;
    int qrow = qrel[q] + q*RRn;
    if (h == 0) g_qrows[q] = qrow;
    g_rel[qrow*HH + h] = srel[h];
    g_loop[idx] = lemb[h];
}

// ---------------- CSR build ----------------
__global__ void k_hist(const int* __restrict__ row, const int* __restrict__ et){
    int e = blockIdx.x*blockDim.x + threadIdx.x;
    if (e >= EN) return;
    atomicAdd(&g_cnt_n[row[e]], 1);
    atomicAdd(&g_cnt_t[et[e]], 1);
}

__global__ void k_scan1(const int* __restrict__ cnt, int* __restrict__ off,
                        int* __restrict__ aux, int n){
    __shared__ int sh[1024];
    int t = threadIdx.x, i = blockIdx.x*1024 + t;
    int v = (i < n) ? cnt[i] : 0;
    sh[t] = v; __syncthreads();
    for (int d = 1; d < 1024; d <<= 1){
        int u = (t >= d) ? sh[t-d] : 0;
        __syncthreads();
        sh[t] += u;
        __syncthreads();
    }
    if (i < n) off[i] = sh[t] - v;
    if (t == 1023) aux[blockIdx.x] = sh[t];
}

__global__ void k_scan2(int* __restrict__ aux, int m){
    __shared__ int sh[64];
    int t = threadIdx.x;
    int v = (t < m) ? aux[t] : 0;
    sh[t] = v; __syncthreads();
    for (int d = 1; d < 64; d <<= 1){
        int u = (t >= d) ? sh[t-d] : 0;
        __syncthreads();
        sh[t] += u;
        __syncthreads();
    }
    if (t < m) aux[t] = sh[t] - v;  // exclusive
}

__global__ void k_scan3(int* __restrict__ off, const int* __restrict__ aux,
                        int* __restrict__ cur, int n, int total){
    int i = blockIdx.x*1024 + threadIdx.x;
    if (i < n){
        int o = off[i] + aux[blockIdx.x];
        off[i] = o; cur[i] = o;
    }
    if (i == 0) off[n] = total;
}

__global__ void k_scatter(const int* __restrict__ col, const int* __restrict__ row,
                          const int* __restrict__ et, const int* __restrict__ eq){
    int e = blockIdx.x*blockDim.x + threadIdx.x;
    if (e >= EN) return;
    int c = col[e], r = row[e], t = et[e], q = eq[e];
    int p  = atomicAdd(&g_cur_n[r], 1);
    g_recN[p] = make_int4(c, t, q, 0);
    int p2 = atomicAdd(&g_cur_t[t], 1);
    g_recT[p2] = make_int4(c, r, q, 0);
}

__global__ void k_dinv2(){
    int n = blockIdx.x*blockDim.x + threadIdx.x;
    if (n >= NN) return;
    int d = g_off_n[n+1] - g_off_n[n];
    g_dinv2[n] = d > 0 ? 1.f/(float)d : 0.f;
}

// ---------------- 64-row x 64(/128)-col projection GEMM with fma.rn.f32x2 ----------------
// out = in @ W[:, co:co+64]^T  (wstride = row stride of W)
template<int TWO, int ACC>
__global__ __launch_bounds__(256, 2) void k_proj(const float* __restrict__ in,
        const float* __restrict__ W, int wstride,
        int co1, float* __restrict__ out1,
        int co2, float* __restrict__ out2){
    __shared__ float In[64][66];       // In[k][row]
    __shared__ float Wt[2][32][66];    // Wt[slice][k32][o]
    int t = threadIdx.x;
    int rowbase = blockIdx.x * 64;
    // load input tile, transposed
    const float4* in4 = (const float4*)(in + (size_t)rowbase*HH);
    for (int idx = t; idx < 1024; idx += 256){
        int r = idx >> 4, kq = idx & 15;
        float4 v = in4[idx];
        In[4*kq+0][r] = v.x; In[4*kq+1][r] = v.y;
        In[4*kq+2][r] = v.z; In[4*kq+3][r] = v.w;
    }
    int op = t & 31, rg = t >> 5;
    int o0 = 2*op;
    ull A0[4], B0[4], A1[4], B1[4];
    ull z = pk2(0.f, 0.f);
    #pragma unroll
    for (int j=0;j<4;j++){ A0[j]=z; B0[j]=z; A1[j]=z; B1[j]=z; }

    for (int half = 0; half < 2; half++){
        __syncthreads();
        for (int idx = t; idx < 2048; idx += 256){
            int k32 = idx & 31, o = idx >> 5;
            Wt[0][k32][o] = W[o*wstride + co1 + half*32 + k32];
            if (TWO) Wt[1][k32][o] = W[o*wstride + co2 + half*32 + k32];
        }
        __syncthreads();
        #pragma unroll 4
        for (int k32 = 0; k32 < 32; k32++){
            const ull* vp = (const ull*)&In[half*32 + k32][rg*8];
            ull v0 = vp[0], v1 = vp[1], v2 = vp[2], v3 = vp[3];
            float2 w = *(const float2*)&Wt[0][k32][o0];
            ull wa = pk2(w.x, w.x), wb = pk2(w.y, w.y);
            ffma2(A0[0], v0, wa); ffma2(A0[1], v1, wa);
            ffma2(A0[2], v2, wa); ffma2(A0[3], v3, wa);
            ffma2(B0[0], v0, wb); ffma2(B0[1], v1, wb);
            ffma2(B0[2], v2, wb); ffma2(B0[3], v3, wb);
            if (TWO){
                float2 w2 = *(const float2*)&Wt[1][k32][o0];
                ull wc = pk2(w2.x, w2.x), wd = pk2(w2.y, w2.y);
                ffma2(A1[0], v0, wc); ffma2(A1[1], v1, wc);
                ffma2(A1[2], v2, wc); ffma2(A1[3], v3, wc);
                ffma2(B1[0], v0, wd); ffma2(B1[1], v1, wd);
                ffma2(B1[2], v2, wd); ffma2(B1[3], v3, wd);
            }
        }
    }
    #pragma unroll
    for (int j = 0; j < 4; j++){
        int r0 = rowbase + rg*8 + 2*j;
        float ax, ay, bx, by;
        upk2(A0[j], ax, ay); upk2(B0[j], bx, by);
        float2 lo = make_float2(ax, bx), hi = make_float2(ay, by);
        float2* p0 = (float2*)(out1 + (size_t)r0*HH + o0);
        float2* p1 = (float2*)(out1 + (size_t)(r0+1)*HH + o0);
        if (ACC){ float2 e0 = *p0, e1 = *p1; lo.x += e0.x; lo.y += e0.y; hi.x += e1.x; hi.y += e1.y; }
        *p0 = lo; *p1 = hi;
        if (TWO){
            upk2(A1[j], ax, ay); upk2(B1[j], bx, by);
            *(float2*)(out2 + (size_t)r0*HH + o0)    = make_float2(ax, bx);
            *(float2*)(out2 + (size_t)(r0+1)*HH + o0) = make_float2(ay, by);
        }
    }
}

// ---------------- act(+bias)(+resid) + LayerNorm, warp per row ----------------
__global__ void k_actln(const float* __restrict__ x, const float* __restrict__ bias,
                        const float* __restrict__ resid, float* __restrict__ out,
                        float* __restrict__ out2, int M){
    int w = (blockIdx.x*blockDim.x + threadIdx.x) >> 5;
    int lane = threadIdx.x & 31;
    if (w >= M) return;
    float2 v = *(const float2*)(x + (size_t)w*HH + 2*lane);
    float2 b = *(const float2*)(bias + 2*lane);
    float y0 = actf(v.x + b.x), y1 = actf(v.y + b.y);
    if (resid){
        float2 rv = *(const float2*)(resid + (size_t)w*HH + 2*lane);
        y0 += rv.x; y1 += rv.y;
    }
    float s = y0 + y1, sq = y0*y0 + y1*y1;
    #pragma unroll
    for (int o=16;o;o>>=1){ s += __shfl_xor_sync(0xffffffffu,s,o); sq += __shfl_xor_sync(0xffffffffu,sq,o); }
    float m = s*(1.f/64.f);
    float var = sq*(1.f/64.f) - m*m;
    float inv = rsqrtf(var + 1e-5f);
    float2 ov = make_float2((y0-m)*inv, (y1-m)*inv);
    *(float2*)(out + (size_t)w*HH + 2*lane) = ov;
    if (out2) *(float2*)(out2 + (size_t)w*HH + 2*lane) = ov;
}

// ---------------- per-relation attention scalars (biases folded in) ----------------
__global__ void k_relscal(const float* __restrict__ Wa, const float* __restrict__ Wb,
                          const float* __restrict__ ba, const float* __restrict__ bb){
    int w = (blockIdx.x*blockDim.x + threadIdx.x) >> 5;
    int lane = threadIdx.x & 31;
    if (w >= RTT) return;
    float2 v = *(const float2*)(g_rel + (size_t)w*HH + 2*lane);
    float a0 = actf(v.x), a1 = actf(v.y);
    float2 wa1 = *(const float2*)(Wa + 2*lane);
    float2 wa2 = *(const float2*)(Wa + 64 + 2*lane);
    float2 wb1 = *(const float2*)(Wb + 2*lane);
    float2 wb2 = *(const float2*)(Wb + 64 + 2*lane);
    float sar = a0*wa1.x + a1*wa1.y;
    float saq = a0*wa2.x + a1*wa2.y;
    float sbr = v.x*wb1.x + v.y*wb1.y;
    float sbq = v.x*wb2.x + v.y*wb2.y;
    #pragma unroll
    for (int o=16;o;o>>=1){
        sar += __shfl_xor_sync(0xffffffffu,sar,o);
        saq += __shfl_xor_sync(0xffffffffu,saq,o);
        sbr += __shfl_xor_sync(0xffffffffu,sbr,o);
        sbq += __shfl_xor_sync(0xffffffffu,sbq,o);
    }
    if (lane == 0){ g_Ar[w]=sar+ba[0]; g_Aq[w]=saq; g_Br[w]=sbr+bb[0]; g_Bq[w]=sbq; }
}

// ---------------- attention sums (no atomics; CSR segment sums) ----------------
__global__ void k_asum(){
    int n = blockIdx.x*blockDim.x + threadIdx.x;
    if (n >= NN) return;
    int b = g_off_n[n], e = g_off_n[n+1];
    float s = 0.f;
    for (int j = b; j < e; j++){
        int4 rc = g_recN[j];
        float a = __expf(g_Ar[rc.y] + g_Aq[rc.z]);
        g_aes[j] = a; s += a;
    }
    g_asum[n] = s;
}

__global__ void k_bsum(){
    int w = (blockIdx.x*blockDim.x + threadIdx.x) >> 5;
    int lane = threadIdx.x & 31;
    if (w >= RTT) return;
    int b = g_off_t[w], e = g_off_t[w+1];
    float br = g_Br[w];
    float s = 0.f;
    for (int j = b + lane; j < e; j += 32){
        int4 rc = g_recT[j];
        float bv = __expf(br + g_Bq[rc.z]);
        g_bes[j] = bv; s += bv;
    }
    #pragma unroll
    for (int o=16;o;o>>=1) s += __shfl_xor_sync(0xffffffffu,s,o);
    if (lane == 0) g_bsum[w] = s;
}

// ---------------- edge message aggregation: warp per node (CSR, no atomics) ----------------
__global__ void k_msg_agg(const int* __restrict__ row, const float* __restrict__ bmsg){
    int w = (blockIdx.x*blockDim.x + threadIdx.x) >> 5;
    int lane = threadIdx.x & 31;
    if (w >= NN) return;
    int b = g_off_n[w], e = g_off_n[w+1];
    // faithful double index: denom = a_sum[row[row_e]] ; row_e == w for whole segment
    float denom = g_asum[row[w]] + 1e-10f;
    float sc0 = g_dinv2[w] / denom;
    float2 bm = *(const float2*)(bmsg + 2*lane);
    float ax = 0.f, ay = 0.f;
    for (int j = b; j < e; j++){
        int4 rc = g_recN[j];
        float coef = g_aes[j] * sc0 * g_dinv2[rc.x];
        float2 ph = *(const float2*)(g_projA + (size_t)rc.x*HH + 2*lane);
        float2 pr = *(const float2*)(g_pr    + (size_t)rc.y*HH + 2*lane);
        float2 pq = *(const float2*)(g_pq    + (size_t)rc.z*HH + 2*lane);
        ax += coef*actf(ph.x + pr.x + pq.x + bm.x);
        ay += coef*actf(ph.y + pr.y + pq.y + bm.y);
    }
    *(float2*)(g_nacc + (size_t)w*HH + 2*lane) = make_float2(ax, ay);
}

// ---------------- ht2r aggregation: warp per relation type (CSR, no atomics) ----------------
__global__ void k_ht2r_agg(const int* __restrict__ et, const float* __restrict__ bht){
    int w = (blockIdx.x*blockDim.x + threadIdx.x) >> 5;
    int lane = threadIdx.x & 31;
    if (w >= RTT) return;
    int b = g_off_t[w], e = g_off_t[w+1];
    // faithful double index: denom = b_sum[et[et_e]] ; et_e == w for whole segment
    float inv_denom = 1.f / (g_bsum[et[w]] + 1e-10f);
    float2 bm = *(const float2*)(bht + 2*lane);
    float ax = 0.f, ay = 0.f;
    for (int j = b; j < e; j++){
        int4 rc = g_recT[j];
        float coef = g_bes[j] * inv_denom;
        float2 ph = *(const float2*)(g_projA + (size_t)rc.x*HH + 2*lane);
        float2 pt = *(const float2*)(g_projB + (size_t)rc.y*HH + 2*lane);
        float2 pq = *(const float2*)(g_pq    + (size_t)rc.z*HH + 2*lane);
        ax += coef*actf(ph.x + pt.x + pq.x + bm.x);
        ay += coef*actf(ph.y + pt.y + pq.y + bm.y);
    }
    *(float2*)(g_racc + (size_t)w*HH + 2*lane) = make_float2(ax, ay);
}

// ---------------- loop update (40 rows) ----------------
__global__ void k_loop(const float* __restrict__ Wl, const float* __restrict__ bl){
    __shared__ float cat[128];
    __shared__ float ps[2], pq2[2];
    int q = blockIdx.x, t = threadIdx.x;   // 64 threads
    int qrow = g_qrows[q];
    float lv = g_loop[q*HH + t];
    cat[t] = lv;
    cat[64+t] = g_rel[qrow*HH + t];
    __syncthreads();
    float s = bl[t];
    #pragma unroll 8
    for (int k=0;k<128;k++) s = fmaf(cat[k], Wl[t*128+k], s);
    float y = lv + actf(s);
    float ss = y, sq = y*y;
    #pragma unroll
    for (int o=16;o;o>>=1){ ss += __shfl_xor_sync(0xffffffffu,ss,o); sq += __shfl_xor_sync(0xffffffffu,sq,o); }
    if ((t&31)==0){ ps[t>>5]=ss; pq2[t>>5]=sq; }
    __syncthreads();
    float S = ps[0]+ps[1], Q = pq2[0]+pq2[1];
    float m = S*(1.f/64.f);
    float var = Q*(1.f/64.f) - m*m;
    float inv = rsqrtf(var + 1e-5f);
    g_loop[q*HH + t] = (y-m)*inv;
}

// ---------------- output means ----------------
__global__ void k_mean(float* __restrict__ out){
    int idx = blockIdx.x*blockDim.x + threadIdx.x;
    if (idx >= 8*201*64) return;
    int h = idx & 63;
    int rb = idx >> 6;
    int r = rb % 201;
    int b = rb / 201;
    float s = 0.f;
    if (r < 200){
        #pragma unroll
        for (int s5=0;s5<5;s5++) s += g_fin[(b*1000 + s5*200 + r)*HH + h];
    } else {
        #pragma unroll
        for (int s5=0;s5<5;s5++) s += g_loop[(b*5 + s5)*HH + h];
    }
    out[idx] = s * 0.2f;
}

// ---------------- host ----------------
struct Ptrs {
    const int *ei,*et,*eq,*hp,*tp,*qr,*lab;
    const float *pos,*srel,*lemb,*Wmsg,*bmsg,*Wht,*bht,*Wa,*ba,*Wb,*bb,*Wl,*bl,*We,*be,*Wr,*br,*Wf,*bf;
};

static void resolve(void* const* d, const int* sz, int n, Ptrs& p){
    int gi, wi;
    if (sz[0] == 2*EN){
        gi = 0;
        wi = (n > 10 && sz[7] == 1 && sz[8] == 1 && sz[9] == 1) ? 10 : 7;
    } else {
        wi = 0; gi = 19;
    }
    p.ei  = (const int*)d[gi+0]; p.et = (const int*)d[gi+1]; p.eq = (const int*)d[gi+2];
    p.hp  = (const int*)d[gi+3]; p.tp = (const int*)d[gi+4]; p.qr = (const int*)d[gi+5];
    p.lab = (const int*)d[gi+6];
    p.pos  = (const float*)d[wi+0];  p.srel = (const float*)d[wi+1];  p.lemb = (const float*)d[wi+2];
    p.Wmsg = (const float*)d[wi+3];  p.bmsg = (const float*)d[wi+4];
    p.Wht  = (const float*)d[wi+5];  p.bht  = (const float*)d[wi+6];
    p.Wa   = (const float*)d[wi+7];  p.ba   = (const float*)d[wi+8];
    p.Wb   = (const float*)d[wi+9];  p.bb   = (const float*)d[wi+10];
    p.Wl   = (const float*)d[wi+11]; p.bl   = (const float*)d[wi+12];
    p.We   = (const float*)d[wi+13]; p.be   = (const float*)d[wi+14];
    p.Wr   = (const float*)d[wi+15]; p.br   = (const float*)d[wi+16];
    p.Wf   = (const float*)d[wi+17]; p.bf   = (const float*)d[wi+18];
}

extern "C" void kernel_launch(void* const* d_in, const int* in_sizes, int n_in,
                              void* d_out, int out_size){
    Ptrs p; resolve(d_in, in_sizes, n_in, p);
    const int* col = p.ei;
    const int* row = p.ei + EN;

    float *s_node, *s_nacc, *s_projA, *s_projB, *s_rel, *s_racc, *s_pr, *s_pq, *s_finals, *s_fin;
    cudaGetSymbolAddress((void**)&s_node,  g_node);
    cudaGetSymbolAddress((void**)&s_nacc,  g_nacc);
    cudaGetSymbolAddress((void**)&s_projA, g_projA);
    cudaGetSymbolAddress((void**)&s_projB, g_projB);
    cudaGetSymbolAddress((void**)&s_rel,   g_rel);
    cudaGetSymbolAddress((void**)&s_racc,  g_racc);
    cudaGetSymbolAddress((void**)&s_pr,    g_pr);
    cudaGetSymbolAddress((void**)&s_pq,    g_pq);
    cudaGetSymbolAddress((void**)&s_finals,g_finals);
    cudaGetSymbolAddress((void**)&s_fin,   g_fin);
    int *s_cnt_n, *s_off_n, *s_cur_n, *s_cnt_t, *s_off_t, *s_cur_t, *s_aux;
    cudaGetSymbolAddress((void**)&s_cnt_n, g_cnt_n);
    cudaGetSymbolAddress((void**)&s_off_n, g_off_n);
    cudaGetSymbolAddress((void**)&s_cur_n, g_cur_n);
    cudaGetSymbolAddress((void**)&s_cnt_t, g_cnt_t);
    cudaGetSymbolAddress((void**)&s_off_t, g_off_t);
    cudaGetSymbolAddress((void**)&s_cur_t, g_cur_t);
    cudaGetSymbolAddress((void**)&s_aux,   g_aux);

    // ---- init + CSR build ----
    k_zero<<<RTT*HH/256,256>>>();
    k_node_init<<<NN*HH/256,256>>>(p.lab, p.pos);
    k_set_rows<<<(BQn*HH+255)/256,256>>>(p.hp, p.pos + 0*HH);
    k_set_rows<<<(BQn*HH+255)/256,256>>>(p.tp, p.pos + 1*HH);
    k_rel_init<<<(BQn*HH+255)/256,256>>>(p.qr, p.srel, p.lemb);
    k_hist<<<EN/256,256>>>(row, p.et);
    k_scan1<<<64,1024>>>(s_cnt_n, s_off_n, s_aux, NN);
    k_scan2<<<1,64>>>(s_aux, 64);
    k_scan3<<<64,1024>>>(s_off_n, s_aux, s_cur_n, NN, EN);
    k_scan1<<<8,1024>>>(s_cnt_t, s_off_t, s_aux, RTT);
    k_scan2<<<1,64>>>(s_aux, 8);
    k_scan3<<<8,1024>>>(s_off_t, s_aux, s_cur_t, RTT, EN);
    k_scatter<<<EN/256,256>>>(col, row, p.et, p.eq);
    k_dinv2<<<NN/256,256>>>();

    for (int i = 0; i < 3; i++){
        const float* Wmsg = p.Wmsg + i*HH*192;
        const float* bmsg = p.bmsg + i*HH;
        const float* Wht  = p.Wht  + i*HH*192;
        const float* bht  = p.bht  + i*HH;
        const float* Wa   = p.Wa + i*128;
        const float* Wb   = p.Wb + i*128;
        const float* We   = p.We + i*HH*HH;
        const float* be   = p.be + i*HH;
        const float* Wr   = p.Wr + i*HH*HH;
        const float* br   = p.br + i*HH;
        const float* Wl   = p.Wl + i*HH*128;
        const float* bl   = p.bl + i*HH;

        k_relscal<<<RTT*32/256,256>>>(Wa, Wb, p.ba + i, p.bb + i);
        // projections for msg phase: Pr, Pq (fused), Ph
        k_proj<1,0><<<RTT/64,256>>>(s_rel,  Wmsg, 192, 64, s_pr, 128, s_pq);
        k_proj<0,0><<<NN/64, 256>>>(s_node, Wmsg, 192, 0,  s_projA, 0, (float*)0);
        k_asum<<<NN/256,256>>>();
        k_bsum<<<RTT*32/256,256>>>();
        k_msg_agg<<<NN*32/256,256>>>(row, bmsg);
        // entity transform: node = LN(act(nacc @ We^T + be))
        k_proj<0,0><<<NN/64,256>>>(s_nacc, We, 64, 0, s_projA, 0, (float*)0);
        k_actln<<<NN*32/256,256>>>(s_projA, be, (const float*)0, s_node, (float*)0, NN);
        // projections for ht2r phase: Ph2+Pt2 (fused), Pq2
        k_proj<1,0><<<NN/64, 256>>>(s_node, Wht, 192, 0, s_projA, 64, s_projB);
        k_proj<0,0><<<RTT/64,256>>>(s_rel,  Wht, 192, 128, s_pq, 0, (float*)0);
        k_ht2r_agg<<<RTT*32/256,256>>>(p.et, bht);
        // relation update: rel = LN(act(racc @ Wr^T + br) + rel); finals[i] = rel
        k_proj<0,0><<<RTT/64,256>>>(s_racc, Wr, 64, 0, s_pr, 0, (float*)0);
        k_actln<<<RTT*32/256,256>>>(s_pr, br, s_rel, s_rel, s_finals + i*RTT*HH, RTT);
        k_loop<<<BQn,64>>>(Wl, bl);
    }

    // final: fin = LN(act(concat(finals) @ Wf^T + bf))
    k_proj<0,0><<<RTT/64,256>>>(s_finals + 0*RTT*HH, p.Wf, 192, 0,   s_fin, 0, (float*)0);
    k_proj<0,1><<<RTT/64,256>>>(s_finals + 1*RTT*HH, p.Wf, 192, 64,  s_fin, 0, (float*)0);
    k_proj<0,1><<<RTT/64,256>>>(s_finals + 2*RTT*HH, p.Wf, 192, 128, s_fin, 0, (float*)0);
    k_actln<<<RTT*32/256,256>>>(s_fin, p.bf, (const float*)0, s_fin, (float*)0, RTT);

    k_mean<<<(8*201*64+255)/256,256>>>((float*)d_out);
}